// round 1
// baseline (speedup 1.0000x reference)
#include <cuda_runtime.h>

// HMM forward algorithm, fused one-hot decode + scaled recurrence.
// B=512 sequences, T=4096 steps, S=64 states, M=125 emission symbols.
// One warp per sequence; each lane owns states (2*lane, 2*lane+1).
// A kept in registers as f32x2-packed k-pairs; alpha broadcast via SMEM.
// Renormalize every NB=8 steps (scaling telescopes exactly).

#define BATCH 512
#define T_LEN 4096
#define S_DIM 64
#define M_DIM 125
#define WARPS_PER_CTA 4
#define ROW_BYTES (M_DIM * 4)   /* 500 */

// ---------- f32x2 helpers (sm_103a packed fp32) ----------
__device__ __forceinline__ unsigned long long pk2(float x, float y) {
    unsigned long long r;
    asm("mov.b64 %0, {%1, %2};" : "=l"(r) : "f"(x), "f"(y));
    return r;
}
__device__ __forceinline__ void upk2(unsigned long long v, float &x, float &y) {
    asm("mov.b64 {%0, %1}, %2;" : "=f"(x), "=f"(y) : "l"(v));
}
__device__ __forceinline__ void ffma2(unsigned long long &d, unsigned long long a,
                                      unsigned long long b) {
    asm("fma.rn.f32x2 %0, %1, %2, %0;" : "+l"(d) : "l"(a), "l"(b));
}
__device__ __forceinline__ unsigned long long fadd2(unsigned long long a,
                                                    unsigned long long b) {
    unsigned long long r;
    asm("add.rn.f32x2 %0, %1, %2;" : "=l"(r) : "l"(a), "l"(b));
    return r;
}

// ---------- one-hot decode ----------
__device__ __forceinline__ float wgt(int i) {
    return ((unsigned)i < (unsigned)M_DIM) ? (float)i : 0.0f;
}
// v = 16 aligned bytes at (row_start & ~15) + 16*lane ; s = (row_start mod 16)/4.
// obs = sum_m m * x[m]  (exact: x is an exact one-hot of small ints).
__device__ __forceinline__ int compute_obs(float4 v, int s, int lane) {
    int b0 = 4 * lane - s;
    float p;
    p = v.x * wgt(b0);
    p = fmaf(v.y, wgt(b0 + 1), p);
    p = fmaf(v.z, wgt(b0 + 2), p);
    p = fmaf(v.w, wgt(b0 + 3), p);
    return __reduce_add_sync(0xffffffffu, (int)p);
}

// Load the 16B-aligned window covering row t of this sequence.
// Row stride 500B; sequence base is 16B-aligned (T*500 % 16 == 0), so
// shift s = t&3 and the window never crosses the end of the buffer
// (s==3 rows end exactly at the row boundary).
__device__ __forceinline__ float4 ldx4(const char* xb, int t, int lane) {
    const float4* p = (const float4*)(xb + (((size_t)(unsigned)t * ROW_BYTES) & ~(size_t)15));
    return __ldcs(p + lane);
}

__global__ void __launch_bounds__(WARPS_PER_CTA * 32, 1)
hmm_forward_kernel(const float* __restrict__ x, const float* __restrict__ I,
                   const float* __restrict__ A, const float* __restrict__ Bm,
                   float* __restrict__ out) {
    __shared__ __align__(16) float sBm[M_DIM * S_DIM];              // 32000 B
    __shared__ __align__(16) float sAlpha[WARPS_PER_CTA][2][S_DIM]; // 2048 B

    const int lane = threadIdx.x & 31;
    const int w    = threadIdx.x >> 5;
    const int seq  = blockIdx.x * WARPS_PER_CTA + w;
    const int j0   = 2 * lane;

    // ---- cooperative Bm -> SMEM ----
    {
        const float4* src = (const float4*)Bm;
        float4* dst = (float4*)sBm;
        for (int i = threadIdx.x; i < (M_DIM * S_DIM) / 4; i += blockDim.x)
            dst[i] = src[i];
    }

    // ---- A columns j0, j0+1 into registers, packed over k-pairs ----
    // A0[p] = (A[2p][j0],   A[2p+1][j0])
    // A1[p] = (A[2p][j0+1], A[2p+1][j0+1])
    unsigned long long A0[32], A1[32];
#pragma unroll
    for (int p = 0; p < 32; p++) {
        float2 ra = *(const float2*)&A[(2 * p) * S_DIM + j0];
        float2 rb = *(const float2*)&A[(2 * p + 1) * S_DIM + j0];
        A0[p] = pk2(ra.x, rb.x);
        A1[p] = pk2(ra.y, rb.y);
    }
    const float i0 = I[j0];
    const float i1 = I[j0 + 1];

    __syncthreads();  // sBm ready

    const char* xb = (const char*)x + (size_t)seq * T_LEN * ROW_BYTES;

    // ---- prime x prefetch ring (distance 4) + emission pipeline ----
    float4 xv[4];
    xv[0] = ldx4(xb, 0, lane);
    xv[1] = ldx4(xb, 1, lane);
    xv[2] = ldx4(xb, 2, lane);
    xv[3] = ldx4(xb, 3, lane);

    int obs0 = compute_obs(xv[0], 0, lane);
    float2 e = *(const float2*)&sBm[obs0 * S_DIM + j0];

    // ---- t = 0 : u = I ∘ E0 ----
    xv[0] = ldx4(xb, 4, lane);  // prefetch row 4 into freed slot 0
    {
        int obsn = compute_obs(xv[1], 1 & 3, lane);
        float2 en = *(const float2*)&sBm[obsn * S_DIM + j0];
        float u0 = i0 * e.x;
        float u1 = i1 * e.y;
        *(float2*)&sAlpha[w][0][j0] = make_float2(u0, u1);
        __syncwarp();
        e = en;
    }
    int buf = 0;
    float ll = 0.0f;

    // One recurrence step. t_i = runtime step index, k_i = compile-time index
    // with t_i ≡ k_i (mod 8) so ring slots / shifts fold to constants.
#define STEP(t_i, k_i, BND_)                                                   \
    do {                                                                       \
        const int tcur = (t_i);                                                \
        if (tcur + 4 < T_LEN) xv[((k_i) + 4) & 3] = ldx4(xb, tcur + 4, lane);  \
        int obsn = 0;                                                          \
        if (tcur + 1 < T_LEN)                                                  \
            obsn = compute_obs(xv[((k_i) + 1) & 3], ((k_i) + 1) & 3, lane);    \
        float2 en = *(const float2*)&sBm[obsn * S_DIM + j0];                   \
        const ulonglong2* ap = (const ulonglong2*)&sAlpha[w][buf][0];          \
        unsigned long long acc0 = 0ull, acc1 = 0ull, acc2 = 0ull, acc3 = 0ull; \
        _Pragma("unroll")                                                      \
        for (int q = 0; q < 16; q++) {                                         \
            ulonglong2 wv = ap[q];                                             \
            ffma2(acc0, wv.x, A0[2 * q]);                                      \
            ffma2(acc1, wv.x, A1[2 * q]);                                      \
            ffma2(acc2, wv.y, A0[2 * q + 1]);                                  \
            ffma2(acc3, wv.y, A1[2 * q + 1]);                                  \
        }                                                                      \
        acc0 = fadd2(acc0, acc2);                                              \
        acc1 = fadd2(acc1, acc3);                                              \
        float r0x, r0y, r1x, r1y;                                              \
        upk2(acc0, r0x, r0y);                                                  \
        upk2(acc1, r1x, r1y);                                                  \
        float u0 = (r0x + r0y) * e.x;                                          \
        float u1 = (r1x + r1y) * e.y;                                          \
        if (BND_) {                                                            \
            float z = u0 + u1;                                                 \
            z += __shfl_xor_sync(0xffffffffu, z, 1);                           \
            z += __shfl_xor_sync(0xffffffffu, z, 2);                           \
            z += __shfl_xor_sync(0xffffffffu, z, 4);                           \
            z += __shfl_xor_sync(0xffffffffu, z, 8);                           \
            z += __shfl_xor_sync(0xffffffffu, z, 16);                          \
            float inv = __fdividef(1.0f, z);                                   \
            ll += __logf(z);                                                   \
            u0 *= inv;                                                         \
            u1 *= inv;                                                         \
        }                                                                      \
        *(float2*)&sAlpha[w][buf ^ 1][j0] = make_float2(u0, u1);               \
        __syncwarp();                                                          \
        buf ^= 1;                                                              \
        e = en;                                                                \
    } while (0)

    // t = 1..7 (fully unrolled so ring indices stay compile-time)
#pragma unroll
    for (int t = 1; t < 8; ++t) STEP(t, t, (t == 7));

    // main blocks of 8; renormalize at k==7 (T divisible by 8 -> final step
    // lands on a boundary, completing ll exactly).
    for (int t0 = 8; t0 < T_LEN; t0 += 8) {
#pragma unroll
        for (int k = 0; k < 8; ++k) STEP(t0 + k, k, (k == 7));
    }
#undef STEP

    if (lane == 0) out[seq] = ll;
}

extern "C" void kernel_launch(void* const* d_in, const int* in_sizes, int n_in,
                              void* d_out, int out_size) {
    const float *x = nullptr, *I = nullptr, *A = nullptr, *Bm = nullptr;
    for (int i = 0; i < n_in; ++i) {
        switch (in_sizes[i]) {
            case BATCH * T_LEN * M_DIM: x  = (const float*)d_in[i]; break; // 262,144,000
            case S_DIM:                 I  = (const float*)d_in[i]; break; // 64
            case S_DIM * S_DIM:         A  = (const float*)d_in[i]; break; // 4096
            case M_DIM * S_DIM:         Bm = (const float*)d_in[i]; break; // 8000
            default: break;
        }
    }
    float* out = (float*)d_out;
    (void)out_size;
    hmm_forward_kernel<<<BATCH / WARPS_PER_CTA, WARPS_PER_CTA * 32>>>(x, I, A, Bm, out);
}

// round 2
// speedup vs baseline: 1.7819x; 1.7819x over previous
#include <cuda_runtime.h>

// HMM forward, fused one-hot decode + scaled recurrence.
// B=512, T=4096, S=64, M=125. One warp per sequence; lane owns states
// (2*lane, 2*lane+1). A held in 128 regs as f32x2 k-pairs; alpha broadcast
// via SMEM double buffer. x prefetched through an 8-deep register ring.
// Renormalization every 8 steps, applied one step late (linear, exact).

#define BATCH 512
#define T_LEN 4096
#define S_DIM 64
#define M_DIM 125
#define WPC 4
#define ROW_BYTES (M_DIM * 4) /* 500 */

typedef unsigned long long ull;

// ---------- f32x2 helpers ----------
__device__ __forceinline__ ull pk2(float x, float y) {
    ull r; asm("mov.b64 %0, {%1, %2};" : "=l"(r) : "f"(x), "f"(y)); return r;
}
__device__ __forceinline__ void upk2(ull v, float &x, float &y) {
    asm("mov.b64 {%0, %1}, %2;" : "=f"(x), "=f"(y) : "l"(v));
}
__device__ __forceinline__ void ffma2(ull &d, ull a, ull b) {
    asm("fma.rn.f32x2 %0, %1, %2, %0;" : "+l"(d) : "l"(a), "l"(b));
}
__device__ __forceinline__ ull fadd2(ull a, ull b) {
    ull r; asm("add.rn.f32x2 %0, %1, %2;" : "=l"(r) : "l"(a), "l"(b)); return r;
}

// ---------- one-hot decode ----------
__device__ __forceinline__ float wgt(int i) {
    return ((unsigned)i < (unsigned)M_DIM) ? (float)i : 0.0f;
}
// v = 16B-aligned window chunk; s = (row_start mod 16)/4 = t mod 4.
__device__ __forceinline__ int compute_obs(float4 v, int s, int lane) {
    int b0 = 4 * lane - s;
    float p;
    p = v.x * wgt(b0);
    p = fmaf(v.y, wgt(b0 + 1), p);
    p = fmaf(v.z, wgt(b0 + 2), p);
    p = fmaf(v.w, wgt(b0 + 3), p);
    return __reduce_add_sync(0xffffffffu, (int)p);
}

// 16B-aligned 512B window covering row t (row stride 500B, seq base 16B-aligned).
__device__ __forceinline__ float4 ldx4(const char* xb, int t, int lane) {
    const float4* p = (const float4*)(xb + (((size_t)(unsigned)t * ROW_BYTES) & ~(size_t)15));
    return __ldcs(p + lane);
}

__global__ void __launch_bounds__(WPC * 32, 1)
hmm_forward_kernel(const float* __restrict__ x, const float* __restrict__ I,
                   const float* __restrict__ A, const float* __restrict__ Bm,
                   float* __restrict__ out) {
    __shared__ __align__(16) float sBm[M_DIM * S_DIM];      // 32000 B
    __shared__ __align__(16) float sAlpha[WPC][2][S_DIM];   // 2048 B

    const int lane = threadIdx.x & 31;
    const int w    = threadIdx.x >> 5;
    const int seq  = blockIdx.x * WPC + w;
    const int j0   = 2 * lane;

    // cooperative Bm -> SMEM
    {
        const float4* src = (const float4*)Bm;
        float4* dst = (float4*)sBm;
        for (int i = threadIdx.x; i < (M_DIM * S_DIM) / 4; i += blockDim.x)
            dst[i] = src[i];
    }

    // A columns j0, j0+1, packed over k-pairs:
    // A0[p] = (A[2p][j0],   A[2p+1][j0]);  A1[p] = same for j0+1.
    ull A0[32], A1[32];
#pragma unroll
    for (int p = 0; p < 32; p++) {
        float2 ra = *(const float2*)&A[(2 * p) * S_DIM + j0];
        float2 rb = *(const float2*)&A[(2 * p + 1) * S_DIM + j0];
        A0[p] = pk2(ra.x, rb.x);
        A1[p] = pk2(ra.y, rb.y);
    }
    const float i0 = I[j0];
    const float i1 = I[j0 + 1];

    __syncthreads();

    const char* xb = (const char*)x + (size_t)seq * T_LEN * ROW_BYTES;

    // prime 8-deep x ring: slot r holds row r
    float4 xv[8];
#pragma unroll
    for (int r = 0; r < 8; r++) xv[r] = ldx4(xb, r, lane);

    int obs0 = compute_obs(xv[0], 0, lane);
    float2 e = *(const float2*)&sBm[obs0 * S_DIM + j0];

    float ll  = 0.0f;
    float inv = 1.0f;  // deferred 1/Z from previous block boundary

    // ---- t = 0 : u = I ∘ E0 (raw), written to buffer 0 ----
    {
        xv[0] = ldx4(xb, 8, lane);  // slot 0 free (row 0 consumed), load row 8
        int obsn = compute_obs(xv[1], 1, lane);
        float2 en = *(const float2*)&sBm[obsn * S_DIM + j0];
        *(float2*)&sAlpha[w][0][j0] = make_float2(i0 * e.x, i1 * e.y);
        __syncwarp();
        e = en;
    }

    // One step. K = t & 7 (compile-time). Step t reads buffer (K+1)&1,
    // writes K&1 (t=0 wrote buffer 0). Prefetch row t+8 into slot t&7.
    // Boundary (K==7): compute z on raw u via butterfly, DO NOT scale;
    // 1/z applied at next K==0 (exact by linearity). Log folds into ll.
#define STEP(t_i, K)                                                           \
    do {                                                                       \
        const int tcur = (t_i);                                                \
        xv[(K) & 7] = ldx4(xb, min(tcur + 8, T_LEN - 1), lane);                \
        int obsn = 0;                                                          \
        if (tcur + 1 < T_LEN)                                                  \
            obsn = compute_obs(xv[((K) + 1) & 7], (tcur + 1) & 3, lane);       \
        float2 en = *(const float2*)&sBm[obsn * S_DIM + j0];                   \
        const ulonglong2* ap =                                                 \
            (const ulonglong2*)&sAlpha[w][((K) + 1) & 1][0];                   \
        ull acc0 = 0ull, acc1 = 0ull, acc2 = 0ull, acc3 = 0ull;                \
        _Pragma("unroll")                                                      \
        for (int q = 0; q < 16; q++) {                                         \
            ulonglong2 wv = ap[q];                                             \
            ffma2(acc0, wv.x, A0[2 * q]);                                      \
            ffma2(acc1, wv.x, A1[2 * q]);                                      \
            ffma2(acc2, wv.y, A0[2 * q + 1]);                                  \
            ffma2(acc3, wv.y, A1[2 * q + 1]);                                  \
        }                                                                      \
        acc0 = fadd2(acc0, acc2);                                              \
        acc1 = fadd2(acc1, acc3);                                              \
        float r0x, r0y, r1x, r1y;                                              \
        upk2(acc0, r0x, r0y);                                                  \
        upk2(acc1, r1x, r1y);                                                  \
        float u0 = (r0x + r0y) * e.x;                                          \
        float u1 = (r1x + r1y) * e.y;                                          \
        if ((K) == 0) { u0 *= inv; u1 *= inv; }                                \
        if ((K) == 7) {                                                        \
            float z = u0 + u1;                                                 \
            z += __shfl_xor_sync(0xffffffffu, z, 1);                           \
            z += __shfl_xor_sync(0xffffffffu, z, 2);                           \
            z += __shfl_xor_sync(0xffffffffu, z, 4);                           \
            z += __shfl_xor_sync(0xffffffffu, z, 8);                           \
            z += __shfl_xor_sync(0xffffffffu, z, 16);                          \
            inv = __fdividef(1.0f, z);                                         \
            ll += __logf(z);                                                   \
        }                                                                      \
        *(float2*)&sAlpha[w][(K) & 1][j0] = make_float2(u0, u1);               \
        __syncwarp();                                                          \
        e = en;                                                                \
    } while (0)

    // first partial block t = 1..7 (K = t; boundary at t=7 defines inv)
#pragma unroll
    for (int t = 1; t < 8; ++t) STEP(t, t);

    // full blocks; T divisible by 8 -> final step t=4095 is a boundary,
    // completing ll exactly (its inv is never needed).
    for (int t0 = 8; t0 < T_LEN; t0 += 8) {
#pragma unroll
        for (int k = 0; k < 8; ++k) STEP(t0 + k, k);
    }
#undef STEP

    if (lane == 0) out[seq] = ll;
}

extern "C" void kernel_launch(void* const* d_in, const int* in_sizes, int n_in,
                              void* d_out, int out_size) {
    const float *x = nullptr, *I = nullptr, *A = nullptr, *Bm = nullptr;
    for (int i = 0; i < n_in; ++i) {
        switch (in_sizes[i]) {
            case BATCH * T_LEN * M_DIM: x  = (const float*)d_in[i]; break;
            case S_DIM:                 I  = (const float*)d_in[i]; break;
            case S_DIM * S_DIM:         A  = (const float*)d_in[i]; break;
            case M_DIM * S_DIM:         Bm = (const float*)d_in[i]; break;
            default: break;
        }
    }
    float* out = (float*)d_out;
    (void)out_size;
    hmm_forward_kernel<<<BATCH / WPC, WPC * 32>>>(x, I, A, Bm, out);
}

// round 3
// speedup vs baseline: 2.3528x; 1.3204x over previous
#include <cuda_runtime.h>

// HMM forward, fused one-hot decode + scaled recurrence.
// B=512, T=4096, S=64, M=125.
// TWO warps per sequence: warp-half h owns output states 32h..32h+31,
// one state per lane. A column per lane in 32 f32x2 registers.
// Alpha exchanged through SMEM double buffer, pair-scoped named barrier.
// Renormalize every 8 steps, applied one step late (linear, exact).

#define BATCH 512
#define T_LEN 4096
#define S_DIM 64
#define M_DIM 125
#define ROW_BYTES (M_DIM * 4) /* 500 */
#define PAIRS 4               /* sequences per CTA */
#define THREADS (PAIRS * 64)  /* 256: 8 warps -> 2 per SMSP */

typedef unsigned long long ull;

// ---------- f32x2 helpers ----------
__device__ __forceinline__ ull pk2(float x, float y) {
    ull r; asm("mov.b64 %0, {%1, %2};" : "=l"(r) : "f"(x), "f"(y)); return r;
}
__device__ __forceinline__ void upk2(ull v, float &x, float &y) {
    asm("mov.b64 {%0, %1}, %2;" : "=f"(x), "=f"(y) : "l"(v));
}
__device__ __forceinline__ void ffma2(ull &d, ull a, ull b) {
    asm("fma.rn.f32x2 %0, %1, %2, %0;" : "+l"(d) : "l"(a), "l"(b));
}
__device__ __forceinline__ ull fadd2(ull a, ull b) {
    ull r; asm("add.rn.f32x2 %0, %1, %2;" : "=l"(r) : "l"(a), "l"(b)); return r;
}

// ---------- one-hot decode ----------
__device__ __forceinline__ float wgt(int i) {
    return ((unsigned)i < (unsigned)M_DIM) ? (float)i : 0.0f;
}
__device__ __forceinline__ int compute_obs(float4 v, int s, int lane) {
    int b0 = 4 * lane - s;
    float p;
    p = v.x * wgt(b0);
    p = fmaf(v.y, wgt(b0 + 1), p);
    p = fmaf(v.z, wgt(b0 + 2), p);
    p = fmaf(v.w, wgt(b0 + 3), p);
    return __reduce_add_sync(0xffffffffu, (int)p);
}

// 16B-aligned 512B window covering row t (row stride 500B, seq base 16B-aligned).
__device__ __forceinline__ float4 ldx4(const char* xb, int t, int lane) {
    const float4* p = (const float4*)(xb + (((size_t)(unsigned)t * ROW_BYTES) & ~(size_t)15));
    return p[lane];  // default cached load: pair-mate warp hits L1
}

__device__ __forceinline__ void pair_bar(int pair) {
    asm volatile("bar.sync %0, 64;" :: "r"(pair + 1) : "memory");
}

__global__ void __launch_bounds__(THREADS, 1)
hmm_forward_kernel(const float* __restrict__ x, const float* __restrict__ I,
                   const float* __restrict__ A, const float* __restrict__ Bm,
                   float* __restrict__ out) {
    __shared__ __align__(16) float sBm[M_DIM * S_DIM];       // 32000 B
    __shared__ __align__(16) float sAlpha[PAIRS][2][S_DIM];  // 2048 B
    __shared__ float sZ[PAIRS][2];                           // boundary partials

    const int lane = threadIdx.x & 31;
    const int w    = threadIdx.x >> 5;
    const int pair = w >> 1;         // 0..3 : sequence within CTA
    const int half = w & 1;          // which 32-state half this warp owns
    const int seq  = blockIdx.x * PAIRS + pair;
    const int j    = half * 32 + lane;  // output state owned by this lane

    // cooperative Bm -> SMEM
    {
        const float4* src = (const float4*)Bm;
        float4* dst = (float4*)sBm;
        for (int i = threadIdx.x; i < (M_DIM * S_DIM) / 4; i += blockDim.x)
            dst[i] = src[i];
    }

    // A column j, packed over k-pairs: Ac[p] = (A[2p][j], A[2p+1][j])
    ull Ac[32];
#pragma unroll
    for (int p = 0; p < 32; p++)
        Ac[p] = pk2(A[(2 * p) * S_DIM + j], A[(2 * p + 1) * S_DIM + j]);
    const float Ij = I[j];

    __syncthreads();  // sBm ready

    const char* xb = (const char*)x + (size_t)seq * T_LEN * ROW_BYTES;

    // prime 8-deep x ring
    float4 xv[8];
#pragma unroll
    for (int r = 0; r < 8; r++) xv[r] = ldx4(xb, r, lane);

    int obs0 = compute_obs(xv[0], 0, lane);
    float e = sBm[obs0 * S_DIM + j];

    float ll  = 0.0f;  // accumulated only in half==0
    float inv = 1.0f;  // deferred 1/Z (applied at K==0)

    // ---- t = 0 : u = I ∘ E0 (raw) into buffer 0 ----
    {
        xv[0] = ldx4(xb, 8, lane);
        int obsn = compute_obs(xv[1], 1, lane);
        float en = sBm[obsn * S_DIM + j];
        sAlpha[pair][0][j] = Ij * e;
        pair_bar(pair);
        e = en;
    }

    // Step t (K = t&7, compile-time): reads buffer (K+1)&1, writes K&1.
    // K==7: butterfly-reduce raw u per warp, store partial to sZ (unscaled).
    // K==0: combine partials -> z, inv = 1/z applied to this step's u,
    //        ll += log z (half 0 only). Exact by linearity of scaling.
#define STEP(t_i, K)                                                           \
    do {                                                                       \
        const int tcur = (t_i);                                                \
        xv[(K) & 7] = ldx4(xb, min(tcur + 8, T_LEN - 1), lane);                \
        int obsn = 0;                                                          \
        if (tcur + 1 < T_LEN)                                                  \
            obsn = compute_obs(xv[((K) + 1) & 7], (tcur + 1) & 3, lane);       \
        float en = sBm[obsn * S_DIM + j];                                      \
        float invL = inv;                                                      \
        if ((K) == 0) {                                                        \
            float2 pz = *(const float2*)&sZ[pair][0];                          \
            float z = pz.x + pz.y;                                             \
            invL = __fdividef(1.0f, z);                                        \
            if (half == 0) ll += __logf(z);                                    \
            inv = invL;                                                        \
        }                                                                      \
        const ulonglong2* ap =                                                 \
            (const ulonglong2*)&sAlpha[pair][((K) + 1) & 1][0];                \
        ull a0 = 0ull, a1 = 0ull, a2 = 0ull, a3 = 0ull;                        \
        _Pragma("unroll")                                                      \
        for (int q = 0; q < 16; q++) {                                         \
            ulonglong2 wv = ap[q];                                             \
            if (q & 1) {                                                       \
                ffma2(a2, wv.x, Ac[2 * q]);                                    \
                ffma2(a3, wv.y, Ac[2 * q + 1]);                                \
            } else {                                                           \
                ffma2(a0, wv.x, Ac[2 * q]);                                    \
                ffma2(a1, wv.y, Ac[2 * q + 1]);                                \
            }                                                                  \
        }                                                                      \
        ull s2 = fadd2(fadd2(a0, a2), fadd2(a1, a3));                          \
        float sx, sy;                                                          \
        upk2(s2, sx, sy);                                                      \
        float u = (sx + sy) * e;                                               \
        if ((K) == 0) u *= invL;                                               \
        if ((K) == 7) {                                                        \
            float zp = u;                                                      \
            zp += __shfl_xor_sync(0xffffffffu, zp, 1);                         \
            zp += __shfl_xor_sync(0xffffffffu, zp, 2);                         \
            zp += __shfl_xor_sync(0xffffffffu, zp, 4);                         \
            zp += __shfl_xor_sync(0xffffffffu, zp, 8);                         \
            zp += __shfl_xor_sync(0xffffffffu, zp, 16);                        \
            if (lane == 0) sZ[pair][half] = zp;                                \
        }                                                                      \
        sAlpha[pair][(K) & 1][j] = u;                                          \
        pair_bar(pair);                                                        \
        e = en;                                                                \
    } while (0)

    // first partial block t = 1..7
#pragma unroll
    for (int t = 1; t < 8; ++t) STEP(t, t);

    // full blocks; final step t=4095 is a boundary (partials stored)
    for (int t0 = 8; t0 < T_LEN; t0 += 8) {
#pragma unroll
        for (int k = 0; k < 8; ++k) STEP(t0 + k, k);
    }
#undef STEP

    // fold in the final boundary's z (its inv is never needed)
    {
        float2 pz = *(const float2*)&sZ[pair][0];
        float z = pz.x + pz.y;
        if (half == 0) {
            ll += __logf(z);
            if (lane == 0) out[seq] = ll;
        }
    }
}

extern "C" void kernel_launch(void* const* d_in, const int* in_sizes, int n_in,
                              void* d_out, int out_size) {
    const float *x = nullptr, *I = nullptr, *A = nullptr, *Bm = nullptr;
    for (int i = 0; i < n_in; ++i) {
        switch (in_sizes[i]) {
            case BATCH * T_LEN * M_DIM: x  = (const float*)d_in[i]; break;
            case S_DIM:                 I  = (const float*)d_in[i]; break;
            case S_DIM * S_DIM:         A  = (const float*)d_in[i]; break;
            case M_DIM * S_DIM:         Bm = (const float*)d_in[i]; break;
            default: break;
        }
    }
    float* out = (float*)d_out;
    (void)out_size;
    hmm_forward_kernel<<<BATCH / PAIRS, THREADS>>>(x, I, A, Bm, out);
}